// round 2
// baseline (speedup 1.0000x reference)
#include <cuda_runtime.h>
#include <math.h>

#define BB   64
#define LL   900
#define DD   64
#define TILE 64
#define NKT  15                    // ceil(900/64)
#define SC   0.180336893f          // 0.125 * log2(e)

typedef unsigned long long ull;

// smem carve (floats)
#define QD_STRIDE 130              // dup Q row: 128 + 2 pad (520B, 8B-aligned)
#define KT_STRIDE 66               // transposed K row (264B, 8B-aligned)
#define V_STRIDE  68               // V row (272B, 16B-aligned for STS.128)
#define PD_STRIDE 130              // dup P row
#define OFF_QD 0
#define OFF_KT (OFF_QD + 64*QD_STRIDE)            // 8320
#define OFF_V  (OFF_KT + 64*KT_STRIDE)            // 12544
#define OFF_PD (OFF_V  + 64*V_STRIDE)             // 16896
#define SMEM_FLOATS (OFF_PD + 64*PD_STRIDE)       // 25216
#define SMEM_BYTES  (SMEM_FLOATS * 4)             // 100864

__device__ float g_invl[BB * LL];

__device__ __forceinline__ void fma2(ull &c, ull a, ull b) {
    asm("fma.rn.f32x2 %0, %1, %2, %0;" : "+l"(c) : "l"(a), "l"(b));
}
__device__ __forceinline__ float ex2(float x) {
    float r; asm("ex2.approx.ftz.f32 %0, %1;" : "=f"(r) : "f"(x)); return r;
}
__device__ __forceinline__ float f2lo(ull x) { return __uint_as_float((unsigned)x); }
__device__ __forceinline__ float f2hi(ull x) { return __uint_as_float((unsigned)(x >> 32)); }

__global__ void __launch_bounds__(256, 2)
attn_fused(const float* __restrict__ q, const float* __restrict__ k,
           const float* __restrict__ v, const int* __restrict__ dur,
           float* __restrict__ out, float* __restrict__ score)
{
    extern __shared__ float sm[];
    float* sQd = sm + OFF_QD;   // [64][130]  Q duplicated: [r][2d]=[r][2d+1]=Q[r][d]
    float* sKt = sm + OFF_KT;   // [64][66]   K transposed: [d][c]
    float* sV  = sm + OFF_V;    // [64][68]   V natural:    [kk][d]
    float* sPd = sm + OFF_PD;   // [64][130]  P duplicated: [r][2kk]=[r][2kk+1]=p
    __shared__ float s_invl[TILE];

    const int tid = threadIdx.x;
    const int tx  = tid & 15;
    const int ty  = tid >> 4;
    const int b   = blockIdx.y;
    const int q0  = blockIdx.x * TILE;
    const int durb = dur[b];

    const float* Qb = q + (size_t)b * LL * DD;
    const float* Kb = k + (size_t)b * LL * DD;
    const float* Vb = v + (size_t)b * LL * DD;
    float*       Sb = score + (size_t)b * LL * LL;

    // ---- Load Q tile duplicated (once per block) ----
    #pragma unroll
    for (int w = 0; w < 4; w++) {
        int idx = tid + 256 * w;
        int r = idx >> 4, c4 = (idx & 15) << 2;
        float4 val = make_float4(0.f, 0.f, 0.f, 0.f);
        if (q0 + r < LL) val = *(const float4*)(Qb + (size_t)(q0 + r) * DD + c4);
        float* row = sQd + r * QD_STRIDE + 2 * c4;
        row[0] = val.x; row[1] = val.x; row[2] = val.y; row[3] = val.y;
        row[4] = val.z; row[5] = val.z; row[6] = val.w; row[7] = val.w;
    }

    ull   acc2[4][2] = {};          // PV accumulators: rows ty*4+i, col-pairs 2tx+32u
    float lrow[4]    = {0.f, 0.f, 0.f, 0.f};

    for (int kt = 0; kt < NKT; kt++) {
        const int c0 = kt * TILE;
        __syncthreads();            // prev GEMM2 done (also covers Q load on kt==0)

        // ---- Load K tile transposed + V tile natural ----
        #pragma unroll
        for (int w = 0; w < 4; w++) {
            int idx = tid + 256 * w;
            int r = idx >> 4, c4 = (idx & 15) << 2;
            float4 kv = make_float4(0.f, 0.f, 0.f, 0.f);
            float4 vv = make_float4(0.f, 0.f, 0.f, 0.f);
            if (c0 + r < LL) {
                kv = *(const float4*)(Kb + (size_t)(c0 + r) * DD + c4);
                vv = *(const float4*)(Vb + (size_t)(c0 + r) * DD + c4);
            }
            sKt[(c4 + 0) * KT_STRIDE + r] = kv.x;
            sKt[(c4 + 1) * KT_STRIDE + r] = kv.y;
            sKt[(c4 + 2) * KT_STRIDE + r] = kv.z;
            sKt[(c4 + 3) * KT_STRIDE + r] = kv.w;
            *(float4*)(sV + r * V_STRIDE + c4) = vv;
        }
        __syncthreads();

        // ---- GEMM1: S = Q @ K^T  (f32x2: rows scalar-dup, col pairs) ----
        ull acc1[4][2] = {};
        #pragma unroll 8
        for (int d = 0; d < DD; d++) {
            ull a0 = *(const ull*)(sQd + (ty * 4 + 0) * QD_STRIDE + 2 * d);
            ull a1 = *(const ull*)(sQd + (ty * 4 + 1) * QD_STRIDE + 2 * d);
            ull a2 = *(const ull*)(sQd + (ty * 4 + 2) * QD_STRIDE + 2 * d);
            ull a3 = *(const ull*)(sQd + (ty * 4 + 3) * QD_STRIDE + 2 * d);
            ull b0 = *(const ull*)(sKt + d * KT_STRIDE + 2 * tx);
            ull b1 = *(const ull*)(sKt + d * KT_STRIDE + 2 * tx + 32);
            fma2(acc1[0][0], a0, b0); fma2(acc1[0][1], a0, b1);
            fma2(acc1[1][0], a1, b0); fma2(acc1[1][1], a1, b1);
            fma2(acc1[2][0], a2, b0); fma2(acc1[2][1], a2, b1);
            fma2(acc1[3][0], a3, b0); fma2(acc1[3][1], a3, b1);
        }

        // ---- Epilogue: p = exp(s), write unnormalized p to smem(dup) + gmem ----
        #pragma unroll
        for (int i = 0; i < 4; i++) {
            const int  rg    = q0 + ty * 4 + i;
            const bool rmask = (rg >= durb);
            #pragma unroll
            for (int u = 0; u < 2; u++) {
                const int cA = c0 + 2 * tx + 32 * u;   // even
                float t0 = f2lo(acc1[i][u]) * SC;
                float t1 = f2hi(acc1[i][u]) * SC;
                if (rmask || cA     >= durb) t0 = 0.f;   // exp(0)=1 == exp(-1e-12)
                if (rmask || cA + 1 >= durb) t1 = 0.f;
                if (cA >= LL) { t0 = -INFINITY; t1 = -INFINITY; }  // ex2(-inf)=0
                float p0 = ex2(t0);
                float p1 = ex2(t1);
                lrow[i] += p0 + p1;
                float* pd = sPd + (ty * 4 + i) * PD_STRIDE + 2 * (2 * tx + 32 * u);
                pd[0] = p0; pd[1] = p0; pd[2] = p1; pd[3] = p1;
                if (rg < LL && cA < LL)
                    *(float2*)(Sb + (size_t)rg * LL + cA) = make_float2(p0, p1);
            }
        }
        __syncthreads();

        // ---- GEMM2: out += P @ V ----
        #pragma unroll 8
        for (int kk = 0; kk < TILE; kk++) {
            ull a0 = *(const ull*)(sPd + (ty * 4 + 0) * PD_STRIDE + 2 * kk);
            ull a1 = *(const ull*)(sPd + (ty * 4 + 1) * PD_STRIDE + 2 * kk);
            ull a2 = *(const ull*)(sPd + (ty * 4 + 2) * PD_STRIDE + 2 * kk);
            ull a3 = *(const ull*)(sPd + (ty * 4 + 3) * PD_STRIDE + 2 * kk);
            ull b0 = *(const ull*)(sV + kk * V_STRIDE + 2 * tx);
            ull b1 = *(const ull*)(sV + kk * V_STRIDE + 2 * tx + 32);
            fma2(acc2[0][0], a0, b0); fma2(acc2[0][1], a0, b1);
            fma2(acc2[1][0], a1, b0); fma2(acc2[1][1], a1, b1);
            fma2(acc2[2][0], a2, b0); fma2(acc2[2][1], a2, b1);
            fma2(acc2[3][0], a3, b0); fma2(acc2[3][1], a3, b1);
        }
    }

    // ---- Row sums -> invl (reduce across the 16 tx lanes) ----
    #pragma unroll
    for (int i = 0; i < 4; i++) {
        float l = lrow[i];
        #pragma unroll
        for (int off = 8; off >= 1; off >>= 1)
            l += __shfl_xor_sync(0xffffffffu, l, off);
        if (tx == 0) {
            const float inv = 1.f / l;
            s_invl[ty * 4 + i] = inv;
            const int rg = q0 + ty * 4 + i;
            if (rg < LL) g_invl[b * LL + rg] = inv;
        }
    }
    __syncthreads();

    // ---- out = (P@V) * invl ----
    #pragma unroll
    for (int i = 0; i < 4; i++) {
        const int rg = q0 + ty * 4 + i;
        if (rg < LL) {
            const float inv = s_invl[ty * 4 + i];
            #pragma unroll
            for (int u = 0; u < 2; u++) {
                float2 o = make_float2(f2lo(acc2[i][u]) * inv, f2hi(acc2[i][u]) * inv);
                *(float2*)(out + ((size_t)b * LL + rg) * DD + 2 * tx + 32 * u) = o;
            }
        }
    }
}

// One block per (b, row): score[row] *= invl[row].  225 float4 per row.
__global__ __launch_bounds__(256)
void norm_score(float* __restrict__ score)
{
    const int row = blockIdx.x;                 // 0 .. B*L-1
    const int t   = threadIdx.x;
    if (t >= 225) return;
    const float inv = g_invl[row];
    float4* p = (float4*)(score + (size_t)row * LL) + t;
    float4 s = *p;
    s.x *= inv; s.y *= inv; s.z *= inv; s.w *= inv;
    *p = s;
}

extern "C" void kernel_launch(void* const* d_in, const int* in_sizes, int n_in,
                              void* d_out, int out_size)
{
    const float* q   = (const float*)d_in[0];
    const float* k   = (const float*)d_in[1];
    const float* v   = (const float*)d_in[2];
    const int*   dur = (const int*)d_in[3];

    float* out   = (float*)d_out;
    float* score = out + (size_t)BB * LL * DD;   // tuple (out, score)

    cudaFuncSetAttribute(attn_fused, cudaFuncAttributeMaxDynamicSharedMemorySize, SMEM_BYTES);

    dim3 grd(NKT, BB);
    attn_fused<<<grd, 256, SMEM_BYTES>>>(q, k, v, dur, out, score);
    norm_score<<<BB * LL, 256>>>(score);
}

// round 4
// speedup vs baseline: 1.6928x; 1.6928x over previous
#include <cuda_runtime.h>
#include <cuda_bf16.h>
#include <math.h>
#include <stdint.h>

#define BB 64
#define LL 900
#define DD 64
#define MT 128            // q rows per block
#define NT 64             // kv tile
#define NKT 15
#define SC 0.180336893f   // 0.125 * log2(e)

#define STR  72           // smem row stride (bf16 elems): 144B, conflict-free ldmatrix
#define STRB 144

// smem byte offsets
#define SQHI 0            // 128 x STR bf16
#define SQLO 18432
#define SKHI 36864        // 64 x STR
#define SKLO 46080
#define SVHI 55296
#define SVLO 64512
#define SPHI 73728        // 128 x STR
#define SPLO 92160
#define SSL   110592      // float[128] rowsums
#define SSINV 111104      // float[128]
#define SMEM_BYTES 111616

__device__ float g_invl[BB * LL];

static __device__ __forceinline__ uint32_t smem_u32(const void* p) {
    uint32_t a;
    asm("{ .reg .u64 t; cvta.to.shared.u64 t, %1; cvt.u32.u64 %0, t; }" : "=r"(a) : "l"(p));
    return a;
}
static __device__ __forceinline__ float ex2f(float x) {
    float r; asm("ex2.approx.ftz.f32 %0, %1;" : "=f"(r) : "f"(x)); return r;
}
static __device__ __forceinline__ void split2(float x, unsigned short &h, unsigned short &l) {
    __nv_bfloat16 hb = __float2bfloat16(x);
    __nv_bfloat16 lb = __float2bfloat16(x - __bfloat162float(hb));
    h = *(unsigned short*)&hb;
    l = *(unsigned short*)&lb;
}
static __device__ __forceinline__ uint32_t pk(unsigned short a, unsigned short b) {
    return (uint32_t)a | ((uint32_t)b << 16);
}

#define LDM4(r, a) \
    asm volatile("ldmatrix.sync.aligned.m8n8.x4.shared.b16 {%0,%1,%2,%3}, [%4];" \
        : "=r"((r)[0]), "=r"((r)[1]), "=r"((r)[2]), "=r"((r)[3]) : "r"(a))
#define LDM4T(r, a) \
    asm volatile("ldmatrix.sync.aligned.m8n8.x4.trans.shared.b16 {%0,%1,%2,%3}, [%4];" \
        : "=r"((r)[0]), "=r"((r)[1]), "=r"((r)[2]), "=r"((r)[3]) : "r"(a))
#define MMA(d, a, b0, b1) \
    asm volatile("mma.sync.aligned.m16n8k16.row.col.f32.bf16.bf16.f32 " \
        "{%0,%1,%2,%3}, {%4,%5,%6,%7}, {%8,%9}, {%0,%1,%2,%3};" \
        : "+f"((d)[0]), "+f"((d)[1]), "+f"((d)[2]), "+f"((d)[3]) \
        : "r"((a)[0]), "r"((a)[1]), "r"((a)[2]), "r"((a)[3]), "r"(b0), "r"(b1))

__global__ void __launch_bounds__(256, 1)
attn_mma(const float* __restrict__ q, const float* __restrict__ k,
         const float* __restrict__ v, const int* __restrict__ dur,
         float* __restrict__ out, float* __restrict__ score)
{
    extern __shared__ char s[];
    const uint32_t sb = smem_u32(s);

    const int tid = threadIdx.x;
    const int l   = tid & 31;
    const int wid = tid >> 5;
    const int mi  = wid >> 1;          // 0..3: 32-row band
    const int ni  = wid & 1;           // 0..1: 32-col half
    const int b   = blockIdx.y;
    const int q0  = blockIdx.x * MT;
    const int durb = dur[b];

    const float* Qb = q + (size_t)b * LL * DD;
    const float* Kb = k + (size_t)b * LL * DD;
    const float* Vb = v + (size_t)b * LL * DD;
    float*       Sb = score + (size_t)b * LL * LL;

    if (tid < 128) *(float*)(s + SSL + tid * 4) = 0.f;

    // ---- load Q -> hi/lo bf16 smem (rows >= L zero) ----
    #pragma unroll
    for (int w = 0; w < 8; w++) {
        int idx = tid + 256 * w;
        int r = idx >> 4, c4 = (idx & 15) << 2;
        float4 val = make_float4(0.f, 0.f, 0.f, 0.f);
        if (q0 + r < LL) val = *(const float4*)(Qb + (size_t)(q0 + r) * DD + c4);
        unsigned short h0,l0,h1,l1,h2,l2,h3,l3;
        split2(val.x,h0,l0); split2(val.y,h1,l1); split2(val.z,h2,l2); split2(val.w,h3,l3);
        uint32_t o = (r * STR + c4) * 2;
        *(uint2*)(s + SQHI + o) = make_uint2(pk(h0,h1), pk(h2,h3));
        *(uint2*)(s + SQLO + o) = make_uint2(pk(l0,l1), pk(l2,l3));
    }

    float oacc[2][4][4];
    #pragma unroll
    for (int a = 0; a < 2; a++)
        #pragma unroll
        for (int nb = 0; nb < 4; nb++)
            #pragma unroll
            for (int j = 0; j < 4; j++) oacc[a][nb][j] = 0.f;
    float rs[2][2] = {{0.f, 0.f}, {0.f, 0.f}};

    // lane address components
    const uint32_t aSel = (l & 16) ? 16u : 0u;   // byte offset: k-col +8 elems
    const uint32_t bRow = (l & 7) + ((l & 16) ? 8 : 0);
    const uint32_t bSel = (l & 8) ? 16u : 0u;
    const uint32_t aRow = (l & 15);

    for (int kt = 0; kt < NKT; kt++) {
        const int c0t = kt * NT;

        // gmem K/V -> regs (before sync, hides latency behind prev GEMM2)
        float4 kreg[4], vreg[4];
        #pragma unroll
        for (int w = 0; w < 4; w++) {
            int idx = tid + 256 * w;
            int r = idx >> 4, c4 = (idx & 15) << 2;
            kreg[w] = make_float4(0.f, 0.f, 0.f, 0.f);
            vreg[w] = make_float4(0.f, 0.f, 0.f, 0.f);
            if (c0t + r < LL) {
                kreg[w] = *(const float4*)(Kb + (size_t)(c0t + r) * DD + c4);
                vreg[w] = *(const float4*)(Vb + (size_t)(c0t + r) * DD + c4);
            }
        }
        __syncthreads();   // prev tile's GEMM2 done with V/P (and Q stores on kt==0)

        #pragma unroll
        for (int w = 0; w < 4; w++) {
            int idx = tid + 256 * w;
            int r = idx >> 4, c4 = (idx & 15) << 2;
            unsigned short h0,l0,h1,l1,h2,l2,h3,l3;
            uint32_t o = (r * STR + c4) * 2;
            split2(kreg[w].x,h0,l0); split2(kreg[w].y,h1,l1);
            split2(kreg[w].z,h2,l2); split2(kreg[w].w,h3,l3);
            *(uint2*)(s + SKHI + o) = make_uint2(pk(h0,h1), pk(h2,h3));
            *(uint2*)(s + SKLO + o) = make_uint2(pk(l0,l1), pk(l2,l3));
            split2(vreg[w].x,h0,l0); split2(vreg[w].y,h1,l1);
            split2(vreg[w].z,h2,l2); split2(vreg[w].w,h3,l3);
            *(uint2*)(s + SVHI + o) = make_uint2(pk(h0,h1), pk(h2,h3));
            *(uint2*)(s + SVLO + o) = make_uint2(pk(l0,l1), pk(l2,l3));
        }
        __syncthreads();

        // ---- GEMM1: S = Q K^T (3-term split) ----
        float sacc[2][4][4];
        #pragma unroll
        for (int a = 0; a < 2; a++)
            #pragma unroll
            for (int nb = 0; nb < 4; nb++)
                #pragma unroll
                for (int j = 0; j < 4; j++) sacc[a][nb][j] = 0.f;

        #pragma unroll
        for (int ks = 0; ks < 4; ks++) {
            const uint32_t kb = ks * 32;     // byte col offset (16 elems)
            uint32_t ahi[2][4], alo[2][4], bhi[2][4], blo[2][4];
            #pragma unroll
            for (int a = 0; a < 2; a++) {
                uint32_t ro = (mi * 32 + a * 16 + aRow) * STRB + kb + aSel;
                LDM4(ahi[a], sb + SQHI + ro);
                LDM4(alo[a], sb + SQLO + ro);
            }
            #pragma unroll
            for (int np = 0; np < 2; np++) {
                uint32_t ro = (ni * 32 + np * 16 + bRow) * STRB + kb + bSel;
                LDM4(bhi[np], sb + SKHI + ro);
                LDM4(blo[np], sb + SKLO + ro);
            }
            #pragma unroll
            for (int a = 0; a < 2; a++)
                #pragma unroll
                for (int np = 0; np < 2; np++) {
                    MMA(sacc[a][2*np],   ahi[a], bhi[np][0], bhi[np][1]);
                    MMA(sacc[a][2*np],   alo[a], bhi[np][0], bhi[np][1]);
                    MMA(sacc[a][2*np],   ahi[a], blo[np][0], blo[np][1]);
                    MMA(sacc[a][2*np+1], ahi[a], bhi[np][2], bhi[np][3]);
                    MMA(sacc[a][2*np+1], alo[a], bhi[np][2], bhi[np][3]);
                    MMA(sacc[a][2*np+1], ahi[a], blo[np][2], blo[np][3]);
                }
        }

        // ---- epilogue: p = exp(mask(S*scale)); P->smem, p->score gmem ----
        #pragma unroll
        for (int a = 0; a < 2; a++) {
            const int R0  = mi * 32 + a * 16 + (l >> 2);
            const int r0g = q0 + R0, r1g = r0g + 8;
            #pragma unroll
            for (int nb = 0; nb < 4; nb++) {
                const int col = ni * 32 + nb * 8 + 2 * (l & 3);
                const int cg  = c0t + col;
                float t0 = sacc[a][nb][0] * SC, t1 = sacc[a][nb][1] * SC;
                float t2 = sacc[a][nb][2] * SC, t3 = sacc[a][nb][3] * SC;
                if (r0g >= durb || cg     >= durb) t0 = 0.f;
                if (r0g >= durb || cg + 1 >= durb) t1 = 0.f;
                if (r1g >= durb || cg     >= durb) t2 = 0.f;
                if (r1g >= durb || cg + 1 >= durb) t3 = 0.f;
                float p0 = ex2f(t0), p1 = ex2f(t1), p2 = ex2f(t2), p3 = ex2f(t3);
                if (cg >= LL) { p0 = 0.f; p1 = 0.f; p2 = 0.f; p3 = 0.f; }
                rs[a][0] += p0 + p1;
                rs[a][1] += p2 + p3;
                unsigned short h0,l0_,h1,l1_;
                split2(p0,h0,l0_); split2(p1,h1,l1_);
                uint32_t o0 = (R0 * STR + col) * 2;
                *(uint32_t*)(s + SPHI + o0) = pk(h0,h1);
                *(uint32_t*)(s + SPLO + o0) = pk(l0_,l1_);
                split2(p2,h0,l0_); split2(p3,h1,l1_);
                uint32_t o1 = ((R0 + 8) * STR + col) * 2;
                *(uint32_t*)(s + SPHI + o1) = pk(h0,h1);
                *(uint32_t*)(s + SPLO + o1) = pk(l0_,l1_);
                if (cg < LL) {
                    if (r0g < LL) *(float2*)(Sb + (size_t)r0g * LL + cg) = make_float2(p0, p1);
                    if (r1g < LL) *(float2*)(Sb + (size_t)r1g * LL + cg) = make_float2(p2, p3);
                }
            }
        }
        __syncthreads();

        // ---- GEMM2: out += P V (V via ldmatrix.trans) ----
        #pragma unroll
        for (int ks = 0; ks < 4; ks++) {
            const uint32_t kb = ks * 32;
            uint32_t ahi[2][4], alo[2][4], bhi[2][4], blo[2][4];
            #pragma unroll
            for (int a = 0; a < 2; a++) {
                uint32_t ro = (mi * 32 + a * 16 + aRow) * STRB + kb + aSel;
                LDM4(ahi[a], sb + SPHI + ro);
                LDM4(alo[a], sb + SPLO + ro);
            }
            #pragma unroll
            for (int np = 0; np < 2; np++) {
                uint32_t ro = (ks * 16 + aRow) * STRB + (ni * 32 + np * 16) * 2 + aSel;
                LDM4T(bhi[np], sb + SVHI + ro);
                LDM4T(blo[np], sb + SVLO + ro);
            }
            #pragma unroll
            for (int a = 0; a < 2; a++)
                #pragma unroll
                for (int np = 0; np < 2; np++) {
                    MMA(oacc[a][2*np],   ahi[a], bhi[np][0], bhi[np][1]);
                    MMA(oacc[a][2*np],   alo[a], bhi[np][0], bhi[np][1]);
                    MMA(oacc[a][2*np],   ahi[a], blo[np][0], blo[np][1]);
                    MMA(oacc[a][2*np+1], ahi[a], bhi[np][2], bhi[np][3]);
                    MMA(oacc[a][2*np+1], alo[a], bhi[np][2], bhi[np][3]);
                    MMA(oacc[a][2*np+1], ahi[a], blo[np][2], blo[np][3]);
                }
        }
    }

    // ---- rowsum reduce -> invl ----
    #pragma unroll
    for (int a = 0; a < 2; a++)
        #pragma unroll
        for (int h = 0; h < 2; h++) {
            float vsum = rs[a][h];
            vsum += __shfl_xor_sync(0xffffffffu, vsum, 1);
            vsum += __shfl_xor_sync(0xffffffffu, vsum, 2);
            if ((l & 3) == 0)
                atomicAdd((float*)(s + SSL) + (mi * 32 + a * 16 + (l >> 2) + 8 * h), vsum);
        }
    __syncthreads();
    if (tid < 128) {
        float inv = 1.f / ((float*)(s + SSL))[tid];
        ((float*)(s + SSINV))[tid] = inv;
        int rg = q0 + tid;
        if (rg < LL) g_invl[b * LL + rg] = inv;
    }
    __syncthreads();

    // ---- out = (P V) * invl ----
    const float* sinv = (const float*)(s + SSINV);
    #pragma unroll
    for (int a = 0; a < 2; a++) {
        const int R0 = mi * 32 + a * 16 + (l >> 2);
        const float inv0 = sinv[R0], inv1 = sinv[R0 + 8];
        const int r0g = q0 + R0, r1g = r0g + 8;
        #pragma unroll
        for (int nb = 0; nb < 4; nb++) {
            const int d0 = ni * 32 + nb * 8 + 2 * (l & 3);
            if (r0g < LL)
                *(float2*)(out + ((size_t)b * LL + r0g) * DD + d0) =
                    make_float2(oacc[a][nb][0] * inv0, oacc[a][nb][1] * inv0);
            if (r1g < LL)
                *(float2*)(out + ((size_t)b * LL + r1g) * DD + d0) =
                    make_float2(oacc[a][nb][2] * inv1, oacc[a][nb][3] * inv1);
        }
    }
}

// score[row] *= invl[row]  (225 float4 per row)
__global__ __launch_bounds__(256)
void norm_score(float* __restrict__ score)
{
    const int row = blockIdx.x;
    const int t   = threadIdx.x;
    if (t >= 225) return;
    const float inv = g_invl[row];
    float4* p = (float4*)(score + (size_t)row * LL) + t;
    float4 sv = *p;
    sv.x *= inv; sv.y *= inv; sv.z *= inv; sv.w *= inv;
    *p = sv;
}

extern "C" void kernel_launch(void* const* d_in, const int* in_sizes, int n_in,
                              void* d_out, int out_size)
{
    const float* q   = (const float*)d_in[0];
    const float* k   = (const float*)d_in[1];
    const float* v   = (const float*)d_in[2];
    const int*   dur = (const int*)d_in[3];

    float* out   = (float*)d_out;
    float* score = out + (size_t)BB * LL * DD;

    cudaFuncSetAttribute(attn_mma, cudaFuncAttributeMaxDynamicSharedMemorySize, SMEM_BYTES);

    dim3 grd(8, BB);       // 8 q-tiles of 128 x 64 batches
    attn_mma<<<grd, 256, SMEM_BYTES>>>(q, k, v, dur, out, score);
    norm_score<<<BB * LL, 256>>>(score);
}